// round 10
// baseline (speedup 1.0000x reference)
#include <cuda_runtime.h>

#define NN   128
#define BB   32
#define INF  4608
#define KSPLIT 36    // 4608 / 128
#define KSEG   128

// ---------------- device scratch ----------------
__device__ float g_qsumP[2 * NN];         // partial qsum per j-half
__device__ float g_q127P[2 * NN];         // partial q127 per j-half
__device__ float g_nsum[NN];              // nsum[d] = sum_n ns[n][d]
__device__ float g_P[KSPLIT * BB * NN];   // split-K partials of x @ Wt
__device__ float g_M0P[2 * NN * NN];      // partial M0T per j-half: [h][i][d]
__device__ float g_out[BB * NN];          // out[b][d]

// ---------------- K1 (fused): ev-reduce (j-halves) -> partial qsum/q127/M0T ; nsum ; input GEMM ----------------
__global__ void __launch_bounds__(256) k_fused1(const float* __restrict__ ev,
                                                const float* __restrict__ ns,
                                                const float* __restrict__ x,
                                                const float* __restrict__ w) {
    int bi = blockIdx.x;
    int t  = threadIdx.x;
    if (bi < 2 * NN) {
        // ---- partial qv[n] = sum_{j in half} ev[i][j][n] (float4 over n) ----
        __shared__ float4 sred[256];
        __shared__ float  qsh[NN];
        __shared__ float  pd[256];
        int i  = bi >> 1;
        int h  = bi & 1;            // j-half
        int n4 = t & 31;            // float4 index over n (32 x 4 = 128)
        int j0 = t >> 5;            // 0..7
        const float4* p = (const float4*)(ev + (size_t)i * NN * NN)
                          + (size_t)(h * 64 + j0) * 32 + n4;
        // 8 batched independent LDG.128 (j = h*64 + j0 + 8r)
        float4 v0 = p[0 * 256], v1 = p[1 * 256], v2 = p[2 * 256], v3 = p[3 * 256];
        float4 v4 = p[4 * 256], v5 = p[5 * 256], v6 = p[6 * 256], v7 = p[7 * 256];
        float4 s01, s23, s45, s67, a;
        s01.x = v0.x + v1.x; s01.y = v0.y + v1.y; s01.z = v0.z + v1.z; s01.w = v0.w + v1.w;
        s23.x = v2.x + v3.x; s23.y = v2.y + v3.y; s23.z = v2.z + v3.z; s23.w = v2.w + v3.w;
        s45.x = v4.x + v5.x; s45.y = v4.y + v5.y; s45.z = v4.z + v5.z; s45.w = v4.w + v5.w;
        s67.x = v6.x + v7.x; s67.y = v6.y + v7.y; s67.z = v6.z + v7.z; s67.w = v6.w + v7.w;
        a.x = (s01.x + s23.x) + (s45.x + s67.x);
        a.y = (s01.y + s23.y) + (s45.y + s67.y);
        a.z = (s01.z + s23.z) + (s45.z + s67.z);
        a.w = (s01.w + s23.w) + (s45.w + s67.w);
        sred[t] = a;
        __syncthreads();
        if (j0 < 4) {
            float4 b = sred[t + 128];
            a.x += b.x; a.y += b.y; a.z += b.z; a.w += b.w;
            sred[t] = a;
        }
        __syncthreads();
        if (j0 < 2) {
            float4 b = sred[t + 64];
            a.x += b.x; a.y += b.y; a.z += b.z; a.w += b.w;
            sred[t] = a;
        }
        __syncthreads();
        if (j0 == 0) {
            float4 b = sred[t + 32];
            a.x += b.x; a.y += b.y; a.z += b.z; a.w += b.w;
            qsh[4 * n4 + 0] = a.x; qsh[4 * n4 + 1] = a.y;
            qsh[4 * n4 + 2] = a.z; qsh[4 * n4 + 3] = a.w;
            if (i == 127) ((float4*)g_q127P)[h * 32 + n4] = a;   // partial Q[n][127]
            float s = a.x + a.y + a.z + a.w;
            #pragma unroll
            for (int off = 16; off > 0; off >>= 1)
                s += __shfl_xor_sync(0xffffffffu, s, off);
            if (n4 == 0) g_qsumP[h * NN + i] = s;
        }
        __syncthreads();
        // partial M0T[h][i][d] = sum_n qsh[n] * ns[n][d]  (split n across 2 halves of threads)
        int d = t & 127, hh = t >> 7;
        float m = 0.f;
        int nb = hh * 64;
        #pragma unroll 8
        for (int k = 0; k < 64; k++) m += qsh[nb + k] * ns[(nb + k) * NN + d];
        pd[t] = m;
        __syncthreads();
        if (t < NN) g_M0P[(h * NN + i) * NN + t] = pd[t] + pd[t + 128];
    } else if (bi == 2 * NN) {
        // ---- nsum[d] = sum_n ns[n][d] ----
        if (t < NN) {
            float acc = 0.f;
            #pragma unroll 16
            for (int n = 0; n < NN; n++) acc += ns[n * NN + t];
            g_nsum[t] = acc;
        }
    } else {
        // ---- input GEMM split-K: idx in [0,144) -> (s, db); single-phase 128-k tile ----
        __shared__ float xs[32 * 129];
        __shared__ float ws[32 * 129];
        int idx = bi - 2 * NN - 1;
        int s   = idx >> 2;          // 0..35
        int db  = idx & 3;           // 0..3
        int k0  = s * KSEG;
        int d0  = db * 32;
        // stage full 32x128 tiles: 1024 float4 each, 4 per thread, batched
        #pragma unroll
        for (int it = 0; it < 4; it++) {
            int e  = t + it * 256;
            int r  = e >> 5, c4 = e & 31;
            float4 xv = *(const float4*)&x[r * INF + k0 + c4 * 4];
            float4 wv = *(const float4*)&w[(d0 + r) * INF + k0 + c4 * 4];
            int o = r * 129 + c4 * 4;
            xs[o + 0] = xv.x; xs[o + 1] = xv.y; xs[o + 2] = xv.z; xs[o + 3] = xv.w;
            ws[o + 0] = wv.x; ws[o + 1] = wv.y; ws[o + 2] = wv.z; ws[o + 3] = wv.w;
        }
        __syncthreads();
        int bq = t & 15, dq = t >> 4;
        float a00 = 0.f, a01 = 0.f, a10 = 0.f, a11 = 0.f;
        #pragma unroll 8
        for (int k = 0; k < KSEG; k++) {
            float xb0 = xs[(2 * bq) * 129 + k];
            float xb1 = xs[(2 * bq + 1) * 129 + k];
            float wd0 = ws[(2 * dq) * 129 + k];
            float wd1 = ws[(2 * dq + 1) * 129 + k];
            a00 += xb0 * wd0; a01 += xb0 * wd1;
            a10 += xb1 * wd0; a11 += xb1 * wd1;
        }
        int b0 = 2 * bq, dl = 2 * dq;
        g_P[(s * BB + b0) * NN + d0 + dl]           = a00;
        g_P[(s * BB + b0) * NN + d0 + dl + 1]       = a01;
        g_P[(s * BB + b0 + 1) * NN + d0 + dl]       = a10;
        g_P[(s * BB + b0 + 1) * NN + d0 + dl + 1]   = a11;
    }
}

// ---------------- K2: fused step1 closed-form + step2 reduction (8-way i-split) ----------------
__global__ void __launch_bounds__(1024) k_final(const float* __restrict__ ib) {
    int b  = blockIdx.x;
    int t  = threadIdx.x;
    int d  = t & 127;
    int iq = t >> 7;                 // 0..7
    __shared__ float qs_s[NN], q127_s[NN], xt_s[NN], s1_s[NN];
    __shared__ float pc[8][NN], ps[8][NN];
    float xp = 0.f;
    #pragma unroll
    for (int s = iq; s < KSPLIT; s += 8) xp += g_P[(s * BB + b) * NN + d];
    pc[iq][d] = xp;
    if (t < NN) {
        qs_s[t]   = g_qsumP[t] + g_qsumP[NN + t];
        q127_s[t] = g_q127P[t] + g_q127P[NN + t];
    }
    __syncthreads();
    if (t < NN) {
        float xt = ib[t];
        #pragma unroll
        for (int q = 0; q < 8; q++) xt += pc[q][t];
        xt_s[t] = xt;
        s1_s[t] = g_nsum[t] + 128.f * xt;
    }
    __syncthreads();
    float xt = xt_s[d], s1 = s1_s[d];
    float c = 0.f, ss = 0.f;
    int i0 = iq * 16;
    #pragma unroll
    for (int k = 0; k < 16; k++) {
        int i = i0 + k;
        float m0 = g_M0P[i * NN + d] + g_M0P[NN * NN + i * NN + d];
        float v = (m0 + xt * qs_s[i]) * s1;
        v = (i == d) ? 0.f : fmaxf(v, 0.f);
        c  += v * q127_s[i];
        ss += v;
    }
    pc[iq][d] = c; ps[iq][d] = ss;
    __syncthreads();
    if (t < NN) {
        float C = 0.f, S = 0.f;
        #pragma unroll
        for (int q = 0; q < 8; q++) { C += pc[q][d]; S += ps[q][d]; }
        float m = C * S;
        if (d == 127) m = 0.f;
        g_out[b * NN + d] = fmaxf(m, 0.f);
    }
}

// ---------------- K3: recreation GEMM (16-feature tiles, LDS.128 inner loop) + scores ----------------
#define FP 34   // padded row width in float4 (136 floats)
__global__ void __launch_bounds__(256) k_heads(const float* __restrict__ rw,
                                               const float* __restrict__ rb,
                                               const float* __restrict__ sw,
                                               const float* __restrict__ sb,
                                               float* __restrict__ out,
                                               int score_off) {
    int bx = blockIdx.x;
    int t  = threadIdx.x;
    if (bx < 288) {
        __shared__ float4 os4[32 * FP];   // os[b][k], pad 136 floats
        __shared__ float4 ws4[16 * FP];   // ws[f][k], pad 136 floats
        int f0 = bx * 16;
        #pragma unroll
        for (int i = 0; i < 4; i++) {
            int e = t + i * 256;
            int r = e >> 5, c4 = e & 31;
            os4[r * FP + c4] = ((const float4*)&g_out[r * NN])[c4];
        }
        #pragma unroll
        for (int i = 0; i < 2; i++) {
            int e = t + i * 256;
            int r = e >> 5, c4 = e & 31;
            ws4[r * FP + c4] = ((const float4*)&rw[(size_t)(f0 + r) * NN])[c4];
        }
        __syncthreads();
        int bq = t >> 4;          // 0..15 -> batches 2bq, 2bq+1
        int fq = t & 15;          // 0..15 -> feature f0+fq
        float a0 = 0.f, a1 = 0.f;
        const float4* osr0 = &os4[(2 * bq) * FP];
        const float4* osr1 = &os4[(2 * bq + 1) * FP];
        const float4* wsr  = &ws4[fq * FP];
        #pragma unroll
        for (int k4 = 0; k4 < 32; k4++) {
            float4 wv  = wsr[k4];
            float4 x0  = osr0[k4];
            float4 x1  = osr1[k4];
            a0 += x0.x * wv.x + x0.y * wv.y + x0.z * wv.z + x0.w * wv.w;
            a1 += x1.x * wv.x + x1.y * wv.y + x1.z * wv.z + x1.w * wv.w;
        }
        float bias = rb[f0 + fq];
        out[(2 * bq) * INF + f0 + fq]     = a0 + bias;
        out[(2 * bq + 1) * INF + f0 + fq] = a1 + bias;
    } else {
        if (t < BB) {
            float acc = sb[0];
            #pragma unroll 8
            for (int d = 0; d < NN; d++) acc += g_out[t * NN + d] * sw[d];
            out[score_off + t] = acc;
        }
    }
}

// ---------------- launch ----------------
extern "C" void kernel_launch(void* const* d_in, const int* in_sizes, int n_in,
                              void* d_out, int out_size) {
    const float* x   = (const float*)d_in[0];
    const float* ipw = (const float*)d_in[1];
    const float* ipb = (const float*)d_in[2];
    const float* ns  = (const float*)d_in[3];
    const float* ev  = (const float*)d_in[4];
    const float* rw  = (const float*)d_in[5];
    const float* rb  = (const float*)d_in[6];
    const float* sw  = (const float*)d_in[7];
    const float* sb  = (const float*)d_in[8];
    float* out = (float*)d_out;

    k_fused1<<<2 * NN + 1 + 144, 256>>>(ev, ns, x, ipw);
    k_final <<<BB, 1024>>>(ipb);
    k_heads <<<289, 256>>>(rw, rb, sw, sb, out, out_size - BB);
}

// round 13
// speedup vs baseline: 1.0860x; 1.0860x over previous
#include <cuda_runtime.h>

#define NN   128
#define BB   32
#define INF  4608
#define KSPLIT 36    // 4608 / 128
#define KSEG   128

// ---------------- device scratch ----------------
__device__ float g_qsum[NN];              // qsum[i] = sum_n Q[n][i]
__device__ float g_q127[NN];              // q127[n] = Q[n][127]
__device__ float g_nsum[NN];              // nsum[d] = sum_n ns[n][d]
__device__ float g_P[KSPLIT * BB * NN];   // split-K partials of x @ Wt
__device__ float g_M0T[NN * NN];          // M0T[i][d] = sum_n ns[n][d] Q[n][i]
__device__ float g_out[BB * NN];          // out[b][d]

// ---------------- K1 (fused): ev-reduce -> qsum/q127/M0T ; nsum ; input GEMM ----------------
__global__ void __launch_bounds__(256) k_fused1(const float* __restrict__ ev,
                                                const float* __restrict__ ns,
                                                const float* __restrict__ x,
                                                const float* __restrict__ w) {
    int bi = blockIdx.x;
    int t  = threadIdx.x;
    if (bi < NN) {
        // ---- per-i: qv[n] = Q[n][i] = sum_j ev[i][j][n], two batches of 8 LDG.128 ----
        __shared__ float4 sred[256];
        __shared__ float  qsh[NN];
        __shared__ float  pd[256];
        int i  = bi;
        int n4 = t & 31;            // float4 index over n (32 x 4 = 128)
        int j0 = t >> 5;            // 0..7
        const float4* p = (const float4*)(ev + (size_t)i * NN * NN)
                          + (size_t)j0 * 32 + n4;
        // batch 1: j = j0 + 8r, r = 0..7  (8 independent LDG.128 in flight)
        float4 v0 = p[0 * 256], v1 = p[1 * 256], v2 = p[2 * 256], v3 = p[3 * 256];
        float4 v4 = p[4 * 256], v5 = p[5 * 256], v6 = p[6 * 256], v7 = p[7 * 256];
        float4 a;
        a.x = ((v0.x + v1.x) + (v2.x + v3.x)) + ((v4.x + v5.x) + (v6.x + v7.x));
        a.y = ((v0.y + v1.y) + (v2.y + v3.y)) + ((v4.y + v5.y) + (v6.y + v7.y));
        a.z = ((v0.z + v1.z) + (v2.z + v3.z)) + ((v4.z + v5.z) + (v6.z + v7.z));
        a.w = ((v0.w + v1.w) + (v2.w + v3.w)) + ((v4.w + v5.w) + (v6.w + v7.w));
        // batch 2: j = 64 + j0 + 8r
        const float4* q = p + 64 * 32;
        float4 u0 = q[0 * 256], u1 = q[1 * 256], u2 = q[2 * 256], u3 = q[3 * 256];
        float4 u4 = q[4 * 256], u5 = q[5 * 256], u6 = q[6 * 256], u7 = q[7 * 256];
        a.x += ((u0.x + u1.x) + (u2.x + u3.x)) + ((u4.x + u5.x) + (u6.x + u7.x));
        a.y += ((u0.y + u1.y) + (u2.y + u3.y)) + ((u4.y + u5.y) + (u6.y + u7.y));
        a.z += ((u0.z + u1.z) + (u2.z + u3.z)) + ((u4.z + u5.z) + (u6.z + u7.z));
        a.w += ((u0.w + u1.w) + (u2.w + u3.w)) + ((u4.w + u5.w) + (u6.w + u7.w));
        sred[t] = a;
        __syncthreads();
        if (j0 < 4) {
            float4 b = sred[t + 128];
            a.x += b.x; a.y += b.y; a.z += b.z; a.w += b.w;
            sred[t] = a;
        }
        __syncthreads();
        if (j0 < 2) {
            float4 b = sred[t + 64];
            a.x += b.x; a.y += b.y; a.z += b.z; a.w += b.w;
            sred[t] = a;
        }
        __syncthreads();
        if (j0 == 0) {
            float4 b = sred[t + 32];
            a.x += b.x; a.y += b.y; a.z += b.z; a.w += b.w;
            qsh[4 * n4 + 0] = a.x; qsh[4 * n4 + 1] = a.y;
            qsh[4 * n4 + 2] = a.z; qsh[4 * n4 + 3] = a.w;
            if (i == 127) ((float4*)g_q127)[n4] = a;       // Q[n][127]
            float s = a.x + a.y + a.z + a.w;
            #pragma unroll
            for (int off = 16; off > 0; off >>= 1)
                s += __shfl_xor_sync(0xffffffffu, s, off);
            if (n4 == 0) g_qsum[i] = s;
        }
        __syncthreads();
        // M0T[i][d] = sum_n qsh[n] * ns[n][d]  (split n across 2 halves of threads)
        int d = t & 127, h = t >> 7;
        float m = 0.f;
        int nb = h * 64;
        #pragma unroll 8
        for (int k = 0; k < 64; k++) m += qsh[nb + k] * ns[(nb + k) * NN + d];
        pd[t] = m;
        __syncthreads();
        if (t < NN) g_M0T[i * NN + t] = pd[t] + pd[t + 128];
    } else if (bi == NN) {
        // ---- nsum[d] = sum_n ns[n][d] ----
        if (t < NN) {
            float acc = 0.f;
            #pragma unroll 16
            for (int n = 0; n < NN; n++) acc += ns[n * NN + t];
            g_nsum[t] = acc;
        }
    } else {
        // ---- input GEMM split-K: idx in [0,144) -> (s, db); single-phase 128-k tile ----
        __shared__ float xs[32 * 129];
        __shared__ float ws[32 * 129];
        int idx = bi - NN - 1;
        int s   = idx >> 2;          // 0..35
        int db  = idx & 3;           // 0..3
        int k0  = s * KSEG;
        int d0  = db * 32;
        #pragma unroll
        for (int it = 0; it < 4; it++) {
            int e  = t + it * 256;
            int r  = e >> 5, c4 = e & 31;
            float4 xv = *(const float4*)&x[r * INF + k0 + c4 * 4];
            float4 wv = *(const float4*)&w[(d0 + r) * INF + k0 + c4 * 4];
            int o = r * 129 + c4 * 4;
            xs[o + 0] = xv.x; xs[o + 1] = xv.y; xs[o + 2] = xv.z; xs[o + 3] = xv.w;
            ws[o + 0] = wv.x; ws[o + 1] = wv.y; ws[o + 2] = wv.z; ws[o + 3] = wv.w;
        }
        __syncthreads();
        int bq = t & 15, dq = t >> 4;
        float a00 = 0.f, a01 = 0.f, a10 = 0.f, a11 = 0.f;
        #pragma unroll 8
        for (int k = 0; k < KSEG; k++) {
            float xb0 = xs[(2 * bq) * 129 + k];
            float xb1 = xs[(2 * bq + 1) * 129 + k];
            float wd0 = ws[(2 * dq) * 129 + k];
            float wd1 = ws[(2 * dq + 1) * 129 + k];
            a00 += xb0 * wd0; a01 += xb0 * wd1;
            a10 += xb1 * wd0; a11 += xb1 * wd1;
        }
        int b0 = 2 * bq, dl = 2 * dq;
        g_P[(s * BB + b0) * NN + d0 + dl]           = a00;
        g_P[(s * BB + b0) * NN + d0 + dl + 1]       = a01;
        g_P[(s * BB + b0 + 1) * NN + d0 + dl]       = a10;
        g_P[(s * BB + b0 + 1) * NN + d0 + dl + 1]   = a11;
    }
}

// ---------------- K2: fused step1 closed-form + step2 reduction (8-way i-split) ----------------
__global__ void __launch_bounds__(1024) k_final(const float* __restrict__ ib) {
    int b  = blockIdx.x;
    int t  = threadIdx.x;
    int d  = t & 127;
    int iq = t >> 7;                 // 0..7
    __shared__ float qs_s[NN], q127_s[NN], xt_s[NN], s1_s[NN];
    __shared__ float pc[8][NN], ps[8][NN];
    float xp = 0.f;
    #pragma unroll
    for (int s = iq; s < KSPLIT; s += 8) xp += g_P[(s * BB + b) * NN + d];
    pc[iq][d] = xp;
    if (t < NN) {
        qs_s[t]   = g_qsum[t];
        q127_s[t] = g_q127[t];
    }
    __syncthreads();
    if (t < NN) {
        float xt = ib[t];
        #pragma unroll
        for (int q = 0; q < 8; q++) xt += pc[q][t];
        xt_s[t] = xt;
        s1_s[t] = g_nsum[t] + 128.f * xt;
    }
    __syncthreads();
    float xt = xt_s[d], s1 = s1_s[d];
    float c = 0.f, ss = 0.f;
    int i0 = iq * 16;
    #pragma unroll
    for (int k = 0; k < 16; k++) {
        int i = i0 + k;
        float v = (g_M0T[i * NN + d] + xt * qs_s[i]) * s1;
        v = (i == d) ? 0.f : fmaxf(v, 0.f);
        c  += v * q127_s[i];
        ss += v;
    }
    pc[iq][d] = c; ps[iq][d] = ss;
    __syncthreads();
    if (t < NN) {
        float C = 0.f, S = 0.f;
        #pragma unroll
        for (int q = 0; q < 8; q++) { C += pc[q][d]; S += ps[q][d]; }
        float m = C * S;
        if (d == 127) m = 0.f;
        g_out[b * NN + d] = fmaxf(m, 0.f);
    }
}

// ---------------- K3: recreation GEMM (16-feature tiles, LDS.128 inner loop) + scores ----------------
#define FP 34   // padded row width in float4 (136 floats)
__global__ void __launch_bounds__(256) k_heads(const float* __restrict__ rw,
                                               const float* __restrict__ rb,
                                               const float* __restrict__ sw,
                                               const float* __restrict__ sb,
                                               float* __restrict__ out,
                                               int score_off) {
    int bx = blockIdx.x;
    int t  = threadIdx.x;
    if (bx < 288) {
        __shared__ float4 os4[32 * FP];   // os[b][k], pad 136 floats
        __shared__ float4 ws4[16 * FP];   // ws[f][k], pad 136 floats
        int f0 = bx * 16;
        #pragma unroll
        for (int i = 0; i < 4; i++) {
            int e = t + i * 256;
            int r = e >> 5, c4 = e & 31;
            os4[r * FP + c4] = ((const float4*)&g_out[r * NN])[c4];
        }
        #pragma unroll
        for (int i = 0; i < 2; i++) {
            int e = t + i * 256;
            int r = e >> 5, c4 = e & 31;
            ws4[r * FP + c4] = ((const float4*)&rw[(size_t)(f0 + r) * NN])[c4];
        }
        __syncthreads();
        int bq = t >> 4;          // 0..15 -> batches 2bq, 2bq+1
        int fq = t & 15;          // 0..15 -> feature f0+fq
        float a0 = 0.f, a1 = 0.f;
        const float4* osr0 = &os4[(2 * bq) * FP];
        const float4* osr1 = &os4[(2 * bq + 1) * FP];
        const float4* wsr  = &ws4[fq * FP];
        #pragma unroll
        for (int k4 = 0; k4 < 32; k4++) {
            float4 wv  = wsr[k4];
            float4 x0  = osr0[k4];
            float4 x1  = osr1[k4];
            a0 += x0.x * wv.x + x0.y * wv.y + x0.z * wv.z + x0.w * wv.w;
            a1 += x1.x * wv.x + x1.y * wv.y + x1.z * wv.z + x1.w * wv.w;
        }
        float bias = rb[f0 + fq];
        out[(2 * bq) * INF + f0 + fq]     = a0 + bias;
        out[(2 * bq + 1) * INF + f0 + fq] = a1 + bias;
    } else {
        if (t < BB) {
            float acc = sb[0];
            #pragma unroll 8
            for (int d = 0; d < NN; d++) acc += g_out[t * NN + d] * sw[d];
            out[score_off + t] = acc;
        }
    }
}

// ---------------- launch ----------------
extern "C" void kernel_launch(void* const* d_in, const int* in_sizes, int n_in,
                              void* d_out, int out_size) {
    const float* x   = (const float*)d_in[0];
    const float* ipw = (const float*)d_in[1];
    const float* ipb = (const float*)d_in[2];
    const float* ns  = (const float*)d_in[3];
    const float* ev  = (const float*)d_in[4];
    const float* rw  = (const float*)d_in[5];
    const float* rb  = (const float*)d_in[6];
    const float* sw  = (const float*)d_in[7];
    const float* sb  = (const float*)d_in[8];
    float* out = (float*)d_out;

    k_fused1<<<NN + 1 + 144, 256>>>(ev, ns, x, ipw);
    k_final <<<BB, 1024>>>(ipb);
    k_heads <<<289, 256>>>(rw, rb, sw, sb, out, out_size - BB);
}